// round 1
// baseline (speedup 1.0000x reference)
#include <cuda_runtime.h>
#include <cstdint>
#include <cstdio>

#define NL   28
#define DIM  1024
#define NH   16
#define HD   64
#define FFN  2816
#define VOCAB 32000

// ---------------- device scratch (no allocations allowed) ----------------
__device__ float g_h[2][DIM];        // residual stream
__device__ float g_qkv[2][3 * DIM];  // q | k | v
__device__ float g_act[2][FFN];      // silu(gate)*up
__device__ float g_hn[2][DIM];       // final normed hidden

// ---------------- helpers ----------------
__device__ __forceinline__ float block_sum(float v) {
    __shared__ float sh[8];
    int lane = threadIdx.x & 31, w = threadIdx.x >> 5;
#pragma unroll
    for (int o = 16; o; o >>= 1) v += __shfl_xor_sync(0xffffffffu, v, o);
    __syncthreads();             // protect sh across sequential calls
    if (lane == 0) sh[w] = v;
    __syncthreads();
    float r = sh[0];
#pragma unroll
    for (int i = 1; i < 8; i++) r += sh[i];
    return r;
}

// block-wide: xs[b][i] = rms(g_h[b]) * gamma[i]  (256 threads)
__device__ __forceinline__ void rms_x(const float* __restrict__ gamma,
                                      float (*xs)[DIM]) {
    int t = threadIdx.x;
    float s0 = 0.f, s1 = 0.f;
    for (int i = t; i < DIM; i += 256) {
        float v0 = g_h[0][i], v1 = g_h[1][i];
        xs[0][i] = v0; xs[1][i] = v1;
        s0 += v0 * v0; s1 += v1 * v1;
    }
    s0 = block_sum(s0);
    s1 = block_sum(s1);
    float r0 = rsqrtf(s0 * (1.f / DIM) + 1e-5f);
    float r1 = rsqrtf(s1 * (1.f / DIM) + 1e-5f);
    for (int i = t; i < DIM; i += 256) {
        float g = gamma[i];
        xs[0][i] *= r0 * g;
        xs[1][i] *= r1 * g;
    }
    __syncthreads();
}

// ---------------- init: residual <- inputs_embeds ----------------
__global__ void k_init(const float* __restrict__ emb) {
    int i = blockIdx.x * blockDim.x + threadIdx.x;
    if (i < 2 * DIM) g_h[i / DIM][i % DIM] = emb[i];
}

// ---------------- K1: rms1 + QKV GEMV. grid 96 x 256 (TILE=32 cols) ------
__global__ void __launch_bounds__(256) k_qkv(const float* __restrict__ wq,
                                             const float* __restrict__ wk,
                                             const float* __restrict__ wv,
                                             const float* __restrict__ ln1) {
    __shared__ float xs[2][DIM];
    rms_x(ln1, xs);

    int t = threadIdx.x;
    int e0 = blockIdx.x * 32;               // in [0, 3072)
    const float* W; int ecol;
    if (e0 < DIM)            { W = wq; ecol = e0; }
    else if (e0 < 2 * DIM)   { W = wk; ecol = e0 - DIM; }
    else                     { W = wv; ecol = e0 - 2 * DIM; }

    int c = t & 7;           // 8 col-threads * float4 = 32 cols
    int stripe = t >> 3;     // 32 d-stripes
    const float* Wp = W + ecol + 4 * c;

    float a00=0,a01=0,a02=0,a03=0,a10=0,a11=0,a12=0,a13=0;
#pragma unroll 8
    for (int d = stripe; d < DIM; d += 32) {
        float4 w4 = *(const float4*)(Wp + (size_t)d * DIM);
        float x0 = xs[0][d], x1 = xs[1][d];
        a00 += x0 * w4.x; a01 += x0 * w4.y; a02 += x0 * w4.z; a03 += x0 * w4.w;
        a10 += x1 * w4.x; a11 += x1 * w4.y; a12 += x1 * w4.z; a13 += x1 * w4.w;
    }
    __shared__ float red[256][8];
    red[t][0]=a00; red[t][1]=a01; red[t][2]=a02; red[t][3]=a03;
    red[t][4]=a10; red[t][5]=a11; red[t][6]=a12; red[t][7]=a13;
#pragma unroll
    for (int off = 128; off >= 8; off >>= 1) {
        __syncthreads();
        if (t < off) {
#pragma unroll
            for (int j = 0; j < 8; j++) red[t][j] += red[t + off][j];
        }
    }
    if (t < 8) {
        int e = e0 + 4 * t;
#pragma unroll
        for (int j = 0; j < 4; j++) {
            g_qkv[0][e + j] = red[t][j];
            g_qkv[1][e + j] = red[t][4 + j];
        }
    }
}

// ---------------- K2: RoPE + attention + O GEMV + residual ---------------
// grid 64 x 256 (TILE=16 cols of Wo)
__global__ void __launch_bounds__(256) k_attn_o(const float* __restrict__ wo,
                                                const int* __restrict__ cpos) {
    __shared__ float xo[2][DIM];   // attention output vector per token
    int t = threadIdx.x;
    int wid = t >> 5, lane = t & 31;
    int pos = cpos[0];

    float inv_freq = __expf(-(float)(2 * lane) * (1.f / HD) * logf(10000.f));
    float ang = (float)pos * inv_freq;
    float cs = cosf(ang), sn = sinf(ang);

#pragma unroll
    for (int p = 0; p < 4; p++) {
        int pair = wid * 4 + p;          // 32 pairs = 2 tokens x 16 heads
        int b = pair >> 4, h = pair & 15;
        const float* q = &g_qkv[b][h * HD];
        const float* k = &g_qkv[b][DIM + h * HD];
        const float* v = &g_qkv[b][2 * DIM + h * HD];
        float q1 = q[lane], q2 = q[lane + 32];
        float k1 = k[lane], k2 = k[lane + 32];
        float q1r = q1 * cs - q2 * sn, q2r = q2 * cs + q1 * sn;
        float k1r = k1 * cs - k2 * sn, k2r = k2 * cs + k1 * sn;
        float dot = q1r * k1r + q2r * k2r;
#pragma unroll
        for (int o = 16; o; o >>= 1) dot += __shfl_xor_sync(0xffffffffu, dot, o);
        float s = dot * 0.125f;
        float m = fmaxf(s, 0.f);
        float es = __expf(s - m);
        float w = es / (es + 2047.f * __expf(-m));
        xo[b][h * HD + lane]      = w * v[lane];
        xo[b][h * HD + lane + 32] = w * v[lane + 32];
    }
    __syncthreads();

    // GEMV xo @ Wo, TILE=16 cols
    int e0 = blockIdx.x * 16;
    int c = t & 3;            // 4 col-threads
    int stripe = t >> 2;      // 64 stripes
    const float* Wp = wo + e0 + 4 * c;
    float a00=0,a01=0,a02=0,a03=0,a10=0,a11=0,a12=0,a13=0;
#pragma unroll 8
    for (int d = stripe; d < DIM; d += 64) {
        float4 w4 = *(const float4*)(Wp + (size_t)d * DIM);
        float x0 = xo[0][d], x1 = xo[1][d];
        a00 += x0 * w4.x; a01 += x0 * w4.y; a02 += x0 * w4.z; a03 += x0 * w4.w;
        a10 += x1 * w4.x; a11 += x1 * w4.y; a12 += x1 * w4.z; a13 += x1 * w4.w;
    }
    __shared__ float red[256][8];
    red[t][0]=a00; red[t][1]=a01; red[t][2]=a02; red[t][3]=a03;
    red[t][4]=a10; red[t][5]=a11; red[t][6]=a12; red[t][7]=a13;
#pragma unroll
    for (int off = 128; off >= 4; off >>= 1) {
        __syncthreads();
        if (t < off) {
#pragma unroll
            for (int j = 0; j < 8; j++) red[t][j] += red[t + off][j];
        }
    }
    if (t < 4) {
        int e = e0 + 4 * t;
#pragma unroll
        for (int j = 0; j < 4; j++) {
            g_h[0][e + j] += red[t][j];
            g_h[1][e + j] += red[t][4 + j];
        }
    }
}

// ---------------- K3: rms2 + gate/up GEMV + SiLU. grid 88 x 256 ----------
__global__ void __launch_bounds__(256) k_gateup(const float* __restrict__ wg,
                                                const float* __restrict__ wu,
                                                const float* __restrict__ ln2) {
    __shared__ float xs[2][DIM];
    rms_x(ln2, xs);

    int t = threadIdx.x;
    int e0 = blockIdx.x * 32;          // in [0, 2816)
    int c = t & 7;
    int stripe = t >> 3;
    const float* Wg = wg + e0 + 4 * c;
    const float* Wu = wu + e0 + 4 * c;

    float g0[4]={0,0,0,0}, g1[4]={0,0,0,0};
    float u0[4]={0,0,0,0}, u1[4]={0,0,0,0};
#pragma unroll 4
    for (int d = stripe; d < DIM; d += 32) {
        float4 wg4 = *(const float4*)(Wg + (size_t)d * FFN);
        float4 wu4 = *(const float4*)(Wu + (size_t)d * FFN);
        float x0 = xs[0][d], x1 = xs[1][d];
        g0[0]+=x0*wg4.x; g0[1]+=x0*wg4.y; g0[2]+=x0*wg4.z; g0[3]+=x0*wg4.w;
        g1[0]+=x1*wg4.x; g1[1]+=x1*wg4.y; g1[2]+=x1*wg4.z; g1[3]+=x1*wg4.w;
        u0[0]+=x0*wu4.x; u0[1]+=x0*wu4.y; u0[2]+=x0*wu4.z; u0[3]+=x0*wu4.w;
        u1[0]+=x1*wu4.x; u1[1]+=x1*wu4.y; u1[2]+=x1*wu4.z; u1[3]+=x1*wu4.w;
    }
    __shared__ float red[256][16];
#pragma unroll
    for (int j = 0; j < 4; j++) {
        red[t][j]      = g0[j];
        red[t][4 + j]  = g1[j];
        red[t][8 + j]  = u0[j];
        red[t][12 + j] = u1[j];
    }
#pragma unroll
    for (int off = 128; off >= 8; off >>= 1) {
        __syncthreads();
        if (t < off) {
#pragma unroll
            for (int j = 0; j < 16; j++) red[t][j] += red[t + off][j];
        }
    }
    if (t < 8) {
        int e = e0 + 4 * t;
#pragma unroll
        for (int j = 0; j < 4; j++) {
            float ga = red[t][j],     ua = red[t][8 + j];
            float gb = red[t][4 + j], ub = red[t][12 + j];
            g_act[0][e + j] = ga / (1.f + __expf(-ga)) * ua;
            g_act[1][e + j] = gb / (1.f + __expf(-gb)) * ub;
        }
    }
}

// ---------------- K4: down GEMV + residual. grid 64 x 256 ----------------
__global__ void __launch_bounds__(256) k_down(const float* __restrict__ wd) {
    __shared__ float xs[2][FFN];
    int t = threadIdx.x;
    for (int i = t; i < FFN; i += 256) {
        xs[0][i] = g_act[0][i];
        xs[1][i] = g_act[1][i];
    }
    __syncthreads();

    int e0 = blockIdx.x * 16;
    int c = t & 3;
    int stripe = t >> 2;         // 64 stripes, 44 iters
    const float* Wp = wd + e0 + 4 * c;
    float a00=0,a01=0,a02=0,a03=0,a10=0,a11=0,a12=0,a13=0;
#pragma unroll 4
    for (int d = stripe; d < FFN; d += 64) {
        float4 w4 = *(const float4*)(Wp + (size_t)d * DIM);
        float x0 = xs[0][d], x1 = xs[1][d];
        a00 += x0 * w4.x; a01 += x0 * w4.y; a02 += x0 * w4.z; a03 += x0 * w4.w;
        a10 += x1 * w4.x; a11 += x1 * w4.y; a12 += x1 * w4.z; a13 += x1 * w4.w;
    }
    __shared__ float red[256][8];
    red[t][0]=a00; red[t][1]=a01; red[t][2]=a02; red[t][3]=a03;
    red[t][4]=a10; red[t][5]=a11; red[t][6]=a12; red[t][7]=a13;
#pragma unroll
    for (int off = 128; off >= 4; off >>= 1) {
        __syncthreads();
        if (t < off) {
#pragma unroll
            for (int j = 0; j < 8; j++) red[t][j] += red[t + off][j];
        }
    }
    if (t < 4) {
        int e = e0 + 4 * t;
#pragma unroll
        for (int j = 0; j < 4; j++) {
            g_h[0][e + j] += red[t][j];
            g_h[1][e + j] += red[t][4 + j];
        }
    }
}

// ---------------- K5: final rms -> d_out[0:2048] and g_hn ----------------
__global__ void __launch_bounds__(256) k_final(const float* __restrict__ normw,
                                               float* __restrict__ out) {
    __shared__ float xs[2][DIM];
    rms_x(normw, xs);
    int t = threadIdx.x;
    for (int i = t; i < DIM; i += 256) {
        g_hn[0][i] = xs[0][i];
        g_hn[1][i] = xs[1][i];
        out[i]       = xs[0][i];
        out[DIM + i] = xs[1][i];
    }
}

// ---------------- K6: lm_head GEMV. grid 500 x 256 (TILE=64) -------------
__global__ void __launch_bounds__(256) k_lmhead(const float* __restrict__ wlm,
                                                float* __restrict__ out) {
    __shared__ float xs[2][DIM];
    int t = threadIdx.x;
    for (int i = t; i < DIM; i += 256) {
        xs[0][i] = g_hn[0][i];
        xs[1][i] = g_hn[1][i];
    }
    __syncthreads();

    int e0 = blockIdx.x * 64;
    int c = t & 15;          // 16 col-threads * float4 = 64 cols
    int stripe = t >> 4;     // 16 stripes, 64 iters
    const float* Wp = wlm + e0 + 4 * c;
    float a00=0,a01=0,a02=0,a03=0,a10=0,a11=0,a12=0,a13=0;
#pragma unroll 8
    for (int d = stripe; d < DIM; d += 16) {
        float4 w4 = *(const float4*)(Wp + (size_t)d * VOCAB);
        float x0 = xs[0][d], x1 = xs[1][d];
        a00 += x0 * w4.x; a01 += x0 * w4.y; a02 += x0 * w4.z; a03 += x0 * w4.w;
        a10 += x1 * w4.x; a11 += x1 * w4.y; a12 += x1 * w4.z; a13 += x1 * w4.w;
    }
    __shared__ float red[256][8];
    red[t][0]=a00; red[t][1]=a01; red[t][2]=a02; red[t][3]=a03;
    red[t][4]=a10; red[t][5]=a11; red[t][6]=a12; red[t][7]=a13;
#pragma unroll
    for (int off = 128; off >= 16; off >>= 1) {
        __syncthreads();
        if (t < off) {
#pragma unroll
            for (int j = 0; j < 8; j++) red[t][j] += red[t + off][j];
        }
    }
    if (t < 16) {
        int e = e0 + 4 * t;
#pragma unroll
        for (int j = 0; j < 4; j++) {
            out[2 * DIM + e + j]         = red[t][j];
            out[2 * DIM + VOCAB + e + j] = red[t][4 + j];
        }
    }
}

// ---------------- launcher ----------------
extern "C" void kernel_launch(void* const* d_in, const int* in_sizes, int n_in,
                              void* d_out, int out_size) {
    const float* emb  = (const float*)d_in[0];
    const int*   cpos = (const int*)d_in[2];
    const float* wq   = (const float*)d_in[4];
    const float* wk   = (const float*)d_in[5];
    const float* wv   = (const float*)d_in[6];
    const float* wo   = (const float*)d_in[7];
    const float* wg   = (const float*)d_in[8];
    const float* wu   = (const float*)d_in[9];
    const float* wd   = (const float*)d_in[10];
    const float* ln1  = (const float*)d_in[11];
    const float* ln2  = (const float*)d_in[12];
    const float* nw   = (const float*)d_in[13];
    const float* wlm  = (const float*)d_in[14];
    float* out = (float*)d_out;

    k_init<<<2, 1024>>>(emb);
    for (int l = 0; l < NL; l++) {
        size_t oqk = (size_t)l * DIM * DIM;
        size_t ogu = (size_t)l * DIM * FFN;
        k_qkv   <<<96, 256>>>(wq + oqk, wk + oqk, wv + oqk, ln1 + l * DIM);
        k_attn_o<<<64, 256>>>(wo + oqk, cpos);
        k_gateup<<<88, 256>>>(wg + ogu, wu + ogu, ln2 + l * DIM);
        k_down  <<<64, 256>>>(wd + ogu);
    }
    k_final <<<1,   256>>>(nw, out);
    k_lmhead<<<500, 256>>>(wlm, out);
}

// round 2
// speedup vs baseline: 1.7444x; 1.7444x over previous
#include <cuda_runtime.h>
#include <cstdint>

#define NL   28
#define DIM  1024
#define NH   16
#define HD   64
#define FFN  2816
#define VOCAB 32000

// ---------------- device scratch ----------------
__device__ float g_h[2][DIM];        // residual stream
__device__ float g_qkv[2][3 * DIM];  // q | k | v
__device__ float g_act[2][FFN];      // silu(gate)*up
__device__ float g_hn[2][DIM];       // final normed hidden

// ---------------- helpers ----------------
__device__ __forceinline__ float block_sum(float v) {
    __shared__ float sh[8];
    int lane = threadIdx.x & 31, w = threadIdx.x >> 5;
#pragma unroll
    for (int o = 16; o; o >>= 1) v += __shfl_xor_sync(0xffffffffu, v, o);
    __syncthreads();
    if (lane == 0) sh[w] = v;
    __syncthreads();
    float r = sh[0];
#pragma unroll
    for (int i = 1; i < 8; i++) r += sh[i];
    return r;
}

// xs[b][i] = rms(g_h[b]) * gamma[i]   (256 threads)
__device__ __forceinline__ void rms_x(const float* __restrict__ gamma,
                                      float (*xs)[DIM]) {
    int t = threadIdx.x;
    float s0 = 0.f, s1 = 0.f;
    for (int i = t; i < DIM; i += 256) {
        float v0 = g_h[0][i], v1 = g_h[1][i];
        xs[0][i] = v0; xs[1][i] = v1;
        s0 += v0 * v0; s1 += v1 * v1;
    }
    s0 = block_sum(s0);
    s1 = block_sum(s1);
    float r0 = rsqrtf(s0 * (1.f / DIM) + 1e-5f);
    float r1 = rsqrtf(s1 * (1.f / DIM) + 1e-5f);
    for (int i = t; i < DIM; i += 256) {
        float g = gamma[i];
        xs[0][i] *= r0 * g;
        xs[1][i] *= r1 * g;
    }
    __syncthreads();
}

// ---------------- init ----------------
__global__ void k_init(const float* __restrict__ emb) {
    int i = blockIdx.x * blockDim.x + threadIdx.x;
    if (i < 2 * DIM) g_h[i / DIM][i % DIM] = emb[i];
}

// ---------------- K1: rms1 + QKV GEMV. grid 384, TILE=8 ------------------
__global__ void __launch_bounds__(256) k_qkv(const float* __restrict__ wq,
                                             const float* __restrict__ wk,
                                             const float* __restrict__ wv,
                                             const float* __restrict__ ln1) {
    __shared__ float xs[2][DIM];
    rms_x(ln1, xs);

    int t = threadIdx.x, lane = t & 31, wid = t >> 5;
    int e0 = blockIdx.x * 8;                // [0, 3072)
    const float* W; int ecol;
    if (e0 < DIM)          { W = wq; ecol = e0; }
    else if (e0 < 2 * DIM) { W = wk; ecol = e0 - DIM; }
    else                   { W = wv; ecol = e0 - 2 * DIM; }

    int c = t & 1;           // 2 float4 col-groups = 8 cols
    int stripe = t >> 1;     // 128 d-stripes, 8 iters
    const float* p = W + ecol + 4 * c + (size_t)stripe * DIM;

    float a[8] = {0,0,0,0,0,0,0,0};
#pragma unroll
    for (int it = 0; it < 8; it++) {
        float4 w4 = *(const float4*)p;
        int d = stripe + it * 128;
        float x0 = xs[0][d], x1 = xs[1][d];
        a[0] += x0*w4.x; a[1] += x0*w4.y; a[2] += x0*w4.z; a[3] += x0*w4.w;
        a[4] += x1*w4.x; a[5] += x1*w4.y; a[6] += x1*w4.z; a[7] += x1*w4.w;
        p += 128 * DIM;
    }
    // warp reduce over stripes (keep c separated: xor >= 2)
#pragma unroll
    for (int o = 16; o >= 2; o >>= 1)
#pragma unroll
        for (int j = 0; j < 8; j++) a[j] += __shfl_xor_sync(0xffffffffu, a[j], o);

    __shared__ float red[8][2][8];
    if (lane < 2)
#pragma unroll
        for (int j = 0; j < 8; j++) red[wid][lane][j] = a[j];
    __syncthreads();
    if (t < 16) {
        int c2 = t >> 3, j = t & 7;
        float s = 0.f;
#pragma unroll
        for (int w = 0; w < 8; w++) s += red[w][c2][j];
        g_qkv[j >> 2][e0 + 4 * c2 + (j & 3)] = s;
    }
}

// ---------------- K2: RoPE + attn + O GEMV + residual. grid 256, TILE=4 --
__global__ void __launch_bounds__(256) k_attn_o(const float* __restrict__ wo,
                                                const int* __restrict__ cpos) {
    __shared__ float xo[2][DIM];
    int t = threadIdx.x, wid = t >> 5, lane = t & 31;
    int pos = cpos[0];

    float inv_freq = __expf(-(float)(2 * lane) * (1.f / HD) * logf(10000.f));
    float ang = (float)pos * inv_freq;
    float cs = cosf(ang), sn = sinf(ang);

#pragma unroll
    for (int pp = 0; pp < 4; pp++) {
        int pair = wid * 4 + pp;        // 32 pairs = 2 tokens x 16 heads
        int b = pair >> 4, h = pair & 15;
        const float* q = &g_qkv[b][h * HD];
        const float* k = &g_qkv[b][DIM + h * HD];
        const float* v = &g_qkv[b][2 * DIM + h * HD];
        float q1 = q[lane], q2 = q[lane + 32];
        float k1 = k[lane], k2 = k[lane + 32];
        float q1r = q1 * cs - q2 * sn, q2r = q2 * cs + q1 * sn;
        float k1r = k1 * cs - k2 * sn, k2r = k2 * cs + k1 * sn;
        float dot = q1r * k1r + q2r * k2r;
#pragma unroll
        for (int o = 16; o; o >>= 1) dot += __shfl_xor_sync(0xffffffffu, dot, o);
        float s = dot * 0.125f;
        float m = fmaxf(s, 0.f);
        float es = __expf(s - m);
        float w = es / (es + 2047.f * __expf(-m));
        xo[b][h * HD + lane]      = w * v[lane];
        xo[b][h * HD + lane + 32] = w * v[lane + 32];
    }
    __syncthreads();

    int e0 = blockIdx.x * 4;
    const float* p = wo + e0 + (size_t)t * DIM;   // stripe = t, 4 iters
    float a[8] = {0,0,0,0,0,0,0,0};
#pragma unroll
    for (int it = 0; it < 4; it++) {
        float4 w4 = *(const float4*)p;
        int d = t + it * 256;
        float x0 = xo[0][d], x1 = xo[1][d];
        a[0] += x0*w4.x; a[1] += x0*w4.y; a[2] += x0*w4.z; a[3] += x0*w4.w;
        a[4] += x1*w4.x; a[5] += x1*w4.y; a[6] += x1*w4.z; a[7] += x1*w4.w;
        p += 256 * DIM;
    }
#pragma unroll
    for (int o = 16; o >= 1; o >>= 1)
#pragma unroll
        for (int j = 0; j < 8; j++) a[j] += __shfl_xor_sync(0xffffffffu, a[j], o);

    __shared__ float red[8][8];
    if (lane == 0)
#pragma unroll
        for (int j = 0; j < 8; j++) red[wid][j] = a[j];
    __syncthreads();
    if (t < 8) {
        float s = 0.f;
#pragma unroll
        for (int w = 0; w < 8; w++) s += red[w][t];
        g_h[t >> 2][e0 + (t & 3)] += s;
    }
}

// ---------------- K3: rms2 + gate/up + SiLU. grid 352, TILE=8 ------------
__global__ void __launch_bounds__(256) k_gateup(const float* __restrict__ wg,
                                                const float* __restrict__ wu,
                                                const float* __restrict__ ln2) {
    __shared__ float xs[2][DIM];
    rms_x(ln2, xs);

    int t = threadIdx.x, lane = t & 31, wid = t >> 5;
    int e0 = blockIdx.x * 8;
    int c = t & 1;
    int stripe = t >> 1;
    const float* pg = wg + e0 + 4 * c + (size_t)stripe * FFN;
    const float* pu = wu + e0 + 4 * c + (size_t)stripe * FFN;

    float a[16];
#pragma unroll
    for (int j = 0; j < 16; j++) a[j] = 0.f;
#pragma unroll
    for (int it = 0; it < 8; it++) {
        float4 wg4 = *(const float4*)pg;
        float4 wu4 = *(const float4*)pu;
        int d = stripe + it * 128;
        float x0 = xs[0][d], x1 = xs[1][d];
        a[0]  += x0*wg4.x; a[1]  += x0*wg4.y; a[2]  += x0*wg4.z; a[3]  += x0*wg4.w;
        a[4]  += x1*wg4.x; a[5]  += x1*wg4.y; a[6]  += x1*wg4.z; a[7]  += x1*wg4.w;
        a[8]  += x0*wu4.x; a[9]  += x0*wu4.y; a[10] += x0*wu4.z; a[11] += x0*wu4.w;
        a[12] += x1*wu4.x; a[13] += x1*wu4.y; a[14] += x1*wu4.z; a[15] += x1*wu4.w;
        pg += 128 * FFN; pu += 128 * FFN;
    }
#pragma unroll
    for (int o = 16; o >= 2; o >>= 1)
#pragma unroll
        for (int j = 0; j < 16; j++) a[j] += __shfl_xor_sync(0xffffffffu, a[j], o);

    __shared__ float red[8][2][16];
    if (lane < 2)
#pragma unroll
        for (int j = 0; j < 16; j++) red[wid][lane][j] = a[j];
    __syncthreads();
    if (t < 16) {
        int c2 = t >> 3, jj = t & 7;       // jj: batch*4+comp
        float sg = 0.f, su = 0.f;
#pragma unroll
        for (int w = 0; w < 8; w++) {
            sg += red[w][c2][jj];
            su += red[w][c2][8 + jj];
        }
        float act = sg / (1.f + __expf(-sg)) * su;
        g_act[jj >> 2][e0 + 4 * c2 + (jj & 3)] = act;
    }
}

// ---------------- K4: down GEMV + residual. grid 256, TILE=4 -------------
__global__ void __launch_bounds__(256) k_down(const float* __restrict__ wd) {
    __shared__ float xs[2][FFN];
    int t = threadIdx.x, lane = t & 31, wid = t >> 5;
    for (int i = t; i < FFN; i += 256) {
        xs[0][i] = g_act[0][i];
        xs[1][i] = g_act[1][i];
    }
    __syncthreads();

    int e0 = blockIdx.x * 4;
    const float* p = wd + e0 + (size_t)t * DIM;    // stripe = t, 11 iters
    float a[8] = {0,0,0,0,0,0,0,0};
#pragma unroll
    for (int it = 0; it < 11; it++) {
        float4 w4 = *(const float4*)p;
        int d = t + it * 256;
        float x0 = xs[0][d], x1 = xs[1][d];
        a[0] += x0*w4.x; a[1] += x0*w4.y; a[2] += x0*w4.z; a[3] += x0*w4.w;
        a[4] += x1*w4.x; a[5] += x1*w4.y; a[6] += x1*w4.z; a[7] += x1*w4.w;
        p += 256 * DIM;
    }
#pragma unroll
    for (int o = 16; o >= 1; o >>= 1)
#pragma unroll
        for (int j = 0; j < 8; j++) a[j] += __shfl_xor_sync(0xffffffffu, a[j], o);

    __shared__ float red[8][8];
    if (lane == 0)
#pragma unroll
        for (int j = 0; j < 8; j++) red[wid][j] = a[j];
    __syncthreads();
    if (t < 8) {
        float s = 0.f;
#pragma unroll
        for (int w = 0; w < 8; w++) s += red[w][t];
        g_h[t >> 2][e0 + (t & 3)] += s;
    }
}

// ---------------- K5: final rms ----------------
__global__ void __launch_bounds__(256) k_final(const float* __restrict__ normw,
                                               float* __restrict__ out) {
    __shared__ float xs[2][DIM];
    rms_x(normw, xs);
    int t = threadIdx.x;
    for (int i = t; i < DIM; i += 256) {
        g_hn[0][i] = xs[0][i];
        g_hn[1][i] = xs[1][i];
        out[i]       = xs[0][i];
        out[DIM + i] = xs[1][i];
    }
}

// ---------------- K6: lm_head GEMV. grid 1000, TILE=32 -------------------
__global__ void __launch_bounds__(256) k_lmhead(const float* __restrict__ wlm,
                                                float* __restrict__ out) {
    __shared__ float xs[2][DIM];
    int t = threadIdx.x, lane = t & 31, wid = t >> 5;
    for (int i = t; i < DIM; i += 256) {
        xs[0][i] = g_hn[0][i];
        xs[1][i] = g_hn[1][i];
    }
    __syncthreads();

    int e0 = blockIdx.x * 32;
    int c = t & 7;           // 8 float4 col-groups = 32 cols
    int stripe = t >> 3;     // 32 stripes, 32 iters
    const float* p = wlm + e0 + 4 * c + (size_t)stripe * VOCAB;

    float a[8] = {0,0,0,0,0,0,0,0};
#pragma unroll 8
    for (int it = 0; it < 32; it++) {
        float4 w4 = *(const float4*)p;
        int d = stripe + it * 32;
        float x0 = xs[0][d], x1 = xs[1][d];
        a[0] += x0*w4.x; a[1] += x0*w4.y; a[2] += x0*w4.z; a[3] += x0*w4.w;
        a[4] += x1*w4.x; a[5] += x1*w4.y; a[6] += x1*w4.z; a[7] += x1*w4.w;
        p += 32 * VOCAB;
    }
    // stripes within warp: bits 3,4 of t -> xor 16, 8
#pragma unroll
    for (int o = 16; o >= 8; o >>= 1)
#pragma unroll
        for (int j = 0; j < 8; j++) a[j] += __shfl_xor_sync(0xffffffffu, a[j], o);

    __shared__ float red[8][8][8];      // [warp][c][j]
    if (lane < 8)
#pragma unroll
        for (int j = 0; j < 8; j++) red[wid][lane][j] = a[j];
    __syncthreads();
    if (t < 64) {
        int c2 = t >> 3, j = t & 7;
        float s = 0.f;
#pragma unroll
        for (int w = 0; w < 8; w++) s += red[w][c2][j];
        out[2 * DIM + (j >> 2) * VOCAB + e0 + 4 * c2 + (j & 3)] = s;
    }
}

// ---------------- launcher ----------------
extern "C" void kernel_launch(void* const* d_in, const int* in_sizes, int n_in,
                              void* d_out, int out_size) {
    const float* emb  = (const float*)d_in[0];
    const int*   cpos = (const int*)d_in[2];
    const float* wq   = (const float*)d_in[4];
    const float* wk   = (const float*)d_in[5];
    const float* wv   = (const float*)d_in[6];
    const float* wo   = (const float*)d_in[7];
    const float* wg   = (const float*)d_in[8];
    const float* wu   = (const float*)d_in[9];
    const float* wd   = (const float*)d_in[10];
    const float* ln1  = (const float*)d_in[11];
    const float* ln2  = (const float*)d_in[12];
    const float* nw   = (const float*)d_in[13];
    const float* wlm  = (const float*)d_in[14];
    float* out = (float*)d_out;

    k_init<<<2, 1024>>>(emb);
    for (int l = 0; l < NL; l++) {
        size_t oqk = (size_t)l * DIM * DIM;
        size_t ogu = (size_t)l * DIM * FFN;
        k_qkv   <<<384, 256>>>(wq + oqk, wk + oqk, wv + oqk, ln1 + l * DIM);
        k_attn_o<<<256, 256>>>(wo + oqk, cpos);
        k_gateup<<<352, 256>>>(wg + ogu, wu + ogu, ln2 + l * DIM);
        k_down  <<<256, 256>>>(wd + ogu);
    }
    k_final <<<1,    256>>>(nw, out);
    k_lmhead<<<1000, 256>>>(wlm, out);
}